// round 16
// baseline (speedup 1.0000x reference)
#include <cuda_runtime.h>
#include <cuda_bf16.h>
#include <math.h>
#include <stdint.h>

// LSTM T=512, B=64, I=H=512 on GB300 (sm_103a via compute_103, HMMA path).
// R16 = R15 (best, 3007us) + warp specialization: warps 0-3 run the recurrent
// h-pipeline, warps 4-7 run the independent x-pipeline one step ahead.
// xpart handoff via parity-double-buffered SMEM (stride-68, conflict-free).
// h-GEMM/x-GEMM: 64x64x128 3-pass bf16-split, 4 warps, warp tile M16xN64.
// Sync: bar.sync 1,128 (h-side), bar.sync 2,128 (x-side), 1 __syncthreads/iter.

#define T_STEPS 512
#define B_SZ    64
#define H_SZ    512
#define I_SZ    512
#define G4      2048
#define NCTA    128
#define NTHR    256
#define KSL     128

#define STRB    272
#define TILEB   (64 * STRB)
#define SM_BIAS 0
#define SM_AX_HI 64
#define SM_AX_LO (SM_AX_HI + TILEB)
#define SM_AH_HI (SM_AX_LO + TILEB)
#define SM_AH_LO (SM_AH_HI + TILEB)
#define SM_WX_HI (SM_AH_LO + TILEB)
#define SM_WX_LO (SM_WX_HI + TILEB)
#define SM_WH_HI (SM_WX_LO + TILEB)
#define SM_WH_LO (SM_WH_HI + TILEB)
#define SM_XP    (SM_WH_LO + TILEB)          // float[2][64*68]
#define SM_TOTAL (SM_XP + 2 * 64 * 68 * 4)   // 174144

#define CPAD 32

__device__ __align__(16) __nv_bfloat16 g_x_hi[T_STEPS * B_SZ * I_SZ];
__device__ __align__(16) __nv_bfloat16 g_x_lo[T_STEPS * B_SZ * I_SZ];
__device__ __align__(16) __nv_bfloat16 g_h_hi[2][B_SZ * H_SZ];
__device__ __align__(16) __nv_bfloat16 g_h_lo[2][B_SZ * H_SZ];
__device__ float g_hp[2][4][G4 * B_SZ];     // combined x+h partials [parity][kg]
__device__ unsigned g_init;
__device__ unsigned g_ph[32 * CPAD];
__device__ unsigned g_elem[32 * CPAD];

__device__ __forceinline__ float sigmoidf_fast(float x) {
    return 1.0f / (1.0f + __expf(-x));
}
__device__ __forceinline__ float tanhf_fast(float x) {
    return 2.0f / (1.0f + __expf(-2.0f * x)) - 1.0f;
}
__device__ __forceinline__ void mma_bf16(float* d, const uint32_t* a, const uint32_t* b) {
    asm volatile(
        "mma.sync.aligned.m16n8k16.row.col.f32.bf16.bf16.f32 "
        "{%0,%1,%2,%3}, {%4,%5,%6,%7}, {%8,%9}, {%0,%1,%2,%3};"
        : "+f"(d[0]), "+f"(d[1]), "+f"(d[2]), "+f"(d[3])
        : "r"(a[0]), "r"(a[1]), "r"(a[2]), "r"(a[3]), "r"(b[0]), "r"(b[1]));
}
__device__ __forceinline__ void ldmatrix_x4(uint32_t r[4], uint32_t addr) {
    asm volatile("ldmatrix.sync.aligned.m8n8.x4.shared.b16 {%0,%1,%2,%3}, [%4];"
                 : "=r"(r[0]), "=r"(r[1]), "=r"(r[2]), "=r"(r[3]) : "r"(addr));
}
__device__ __forceinline__ void ldmatrix_x2(uint32_t r[2], uint32_t addr) {
    asm volatile("ldmatrix.sync.aligned.m8n8.x2.shared.b16 {%0,%1}, [%2];"
                 : "=r"(r[0]), "=r"(r[1]) : "r"(addr));
}
__device__ __forceinline__ uint32_t smem_u32(const void* p) {
    uint32_t a;
    asm("{ .reg .u64 t; cvta.to.shared.u64 t, %1; cvt.u32.u64 %0, t; }" : "=r"(a) : "l"(p));
    return a;
}
__device__ __forceinline__ void signal(unsigned* ctr) {
    asm volatile("red.release.gpu.add.u32 [%0], 1;" :: "l"(ctr) : "memory");
}
__device__ __forceinline__ void wait_ge(unsigned* ctr, unsigned target) {
    unsigned v;
    asm volatile("ld.acquire.gpu.u32 %0, [%1];" : "=r"(v) : "l"(ctr) : "memory");
    while (v < target) {
        __nanosleep(32);
        asm volatile("ld.acquire.gpu.u32 %0, [%1];" : "=r"(v) : "l"(ctr) : "memory");
    }
}
#define BAR_H() asm volatile("bar.sync 1, 128;" ::: "memory")
#define BAR_X() asm volatile("bar.sync 2, 128;" ::: "memory")

// 64x64x128 3-pass bf16-split GEMM, 4 warps, warp tile M16xN64 (8 n-tiles).
__device__ __forceinline__ void gemm_n64(uint32_t a_lane, uint32_t b_lane,
                                         int aoff_hi, int aoff_lo,
                                         int woff_hi, int woff_lo,
                                         float acc[8][4]) {
    #pragma unroll
    for (int ks = 0; ks < 8; ks++) {
        const int kb = ks * 32;
        uint32_t a_hi[4], a_lo[4];
        ldmatrix_x4(a_hi, a_lane + aoff_hi + kb);
        ldmatrix_x4(a_lo, a_lane + aoff_lo + kb);
        #pragma unroll
        for (int nt = 0; nt < 8; nt++) {
            uint32_t b_hi[2], b_lo[2];
            ldmatrix_x2(b_hi, b_lane + nt * (8 * STRB) + woff_hi + kb);
            ldmatrix_x2(b_lo, b_lane + nt * (8 * STRB) + woff_lo + kb);
            mma_bf16(acc[nt], a_hi, b_hi);
            mma_bf16(acc[nt], a_hi, b_lo);
            mma_bf16(acc[nt], a_lo, b_hi);
        }
    }
}

// stage a 64x128 bf16 hi/lo slice with 128 threads (8 uint4 per thread per array)
__device__ __forceinline__ void stage_tile128(char* smem, int dst_hi, int dst_lo,
                                              const __nv_bfloat16* sh,
                                              const __nv_bfloat16* sl, int t128) {
    #pragma unroll
    for (int it = 0; it < 8; it++) {
        int idx = t128 + it * 128;       // 0..1023
        int r   = idx >> 4;
        int c16 = idx & 15;
        uint4 vh = *(const uint4*)(sh + (size_t)r * 512 + c16 * 8);
        uint4 vl = *(const uint4*)(sl + (size_t)r * 512 + c16 * 8);
        int o = r * STRB + c16 * 16;
        *(uint4*)(smem + dst_hi + o) = vh;
        *(uint4*)(smem + dst_lo + o) = vl;
    }
}

extern "C" __global__ void __launch_bounds__(NTHR, 1)
lstm_wspec_kernel(const float* __restrict__ x,
                  const float* __restrict__ hidden0,
                  const float* __restrict__ cell0,
                  const float* __restrict__ W,
                  const float* __restrict__ bias,
                  float* __restrict__ out)
{
    extern __shared__ char smem[];
    float* sbias = (float*)(smem + SM_BIAS);
    float* xp_smem = (float*)(smem + SM_XP);     // [2][64*68]
    const uint32_t sbase = smem_u32(smem);

    const int tid = threadIdx.x;
    const int bid = blockIdx.x;
    const int cg  = bid >> 2;
    const int kg  = bid & 3;
    const int wid = tid >> 5;
    const int lid = tid & 31;
    const bool is_h = (wid < 4);
    const int t128 = tid & 127;          // index within side
    const int mg   = wid & 3;            // M-group (0..3) within side
    const int grp  = lid >> 2;
    const int tg   = lid & 3;

    const uint32_t a_lane = sbase + (uint32_t)(mg * 16 + (lid & 15)) * STRB + (uint32_t)(lid >> 4) * 16;
    const uint32_t b_lane = sbase + (uint32_t)(lid & 7) * STRB + (uint32_t)((lid >> 3) & 1) * 16;

    // ---- init: W_x / W_h slices -> SMEM hi/lo [n'][k] (all 256 threads) ----
    {
        for (int idx = tid; idx < KSL * 64; idx += NTHR) {
            int n = idx & 63;
            int k = idx >> 6;
            int col = (n >> 4) * 512 + cg * 16 + (n & 15);
            int o = n * STRB + k * 2;
            float w0 = W[(size_t)(kg * KSL + k) * G4 + col];
            __nv_bfloat16 h0 = __float2bfloat16_rn(w0);
            *(__nv_bfloat16*)(smem + SM_WX_HI + o) = h0;
            *(__nv_bfloat16*)(smem + SM_WX_LO + o) = __float2bfloat16_rn(w0 - __bfloat162float(h0));
            float w1 = W[(size_t)(512 + kg * KSL + k) * G4 + col];
            __nv_bfloat16 h1 = __float2bfloat16_rn(w1);
            *(__nv_bfloat16*)(smem + SM_WH_HI + o) = h1;
            *(__nv_bfloat16*)(smem + SM_WH_LO + o) = __float2bfloat16_rn(w1 - __bfloat162float(h1));
        }
    }
    if (tid < 16) {
        int gate = tid >> 2;
        int jj   = tid & 3;
        sbias[tid] = bias[gate * H_SZ + cg * 16 + kg * 4 + jj];
    }
    // ---- pre-split x -> bf16 hi/lo (grid-strided, all threads) ----
    {
        const float4* x4 = (const float4*)x;
        const int n4 = T_STEPS * B_SZ * I_SZ / 4;
        for (int i = bid * NTHR + tid; i < n4; i += NCTA * NTHR) {
            float4 v = x4[i];
            __nv_bfloat16 h0 = __float2bfloat16_rn(v.x);
            __nv_bfloat16 h1 = __float2bfloat16_rn(v.y);
            __nv_bfloat16 h2 = __float2bfloat16_rn(v.z);
            __nv_bfloat16 h3 = __float2bfloat16_rn(v.w);
            __nv_bfloat162* dh = (__nv_bfloat162*)(g_x_hi + 4 * (size_t)i);
            dh[0] = __nv_bfloat162(h0, h1);
            dh[1] = __nv_bfloat162(h2, h3);
            __nv_bfloat162* dl = (__nv_bfloat162*)(g_x_lo + 4 * (size_t)i);
            dl[0] = __nv_bfloat162(__float2bfloat16_rn(v.x - __bfloat162float(h0)),
                                   __float2bfloat16_rn(v.y - __bfloat162float(h1)));
            dl[1] = __nv_bfloat162(__float2bfloat16_rn(v.z - __bfloat162float(h2)),
                                   __float2bfloat16_rn(v.w - __bfloat162float(h3)));
        }
    }
    // ---- state init (h-side owns 2 elems per thread) ----
    float cs[2] = {0.f, 0.f};
    float hl[2] = {0.f, 0.f};
    if (is_h) {
        #pragma unroll
        for (int i = 0; i < 2; i++) {
            int e   = t128 + i * 128;        // 0..255
            int eb  = e >> 2;
            int ejj = e & 3;
            int ej  = cg * 16 + kg * 4 + ejj;
            cs[i] = cell0[eb * H_SZ + ej];
            float hv = hidden0[eb * H_SZ + ej];
            __nv_bfloat16 hh = __float2bfloat16_rn(hv);
            g_h_hi[1][eb * H_SZ + ej] = hh;
            g_h_lo[1][eb * H_SZ + ej] = __float2bfloat16_rn(hv - __bfloat162float(hh));
        }
    }

    // ---- init grid barrier ----
    __syncthreads();
    if (tid == 0) {
        signal(&g_init);
        wait_ge(&g_init, NCTA);
    }
    __syncthreads();

    // ---- x prologue: xpart(0) -> xp_smem[0] (x-side only) ----
    if (!is_h) {
        size_t off = (size_t)kg * KSL;
        stage_tile128(smem, SM_AX_HI, SM_AX_LO, g_x_hi + off, g_x_lo + off, t128);
        BAR_X();
        float xacc[8][4];
        #pragma unroll
        for (int i = 0; i < 8; i++) { xacc[i][0]=0.f; xacc[i][1]=0.f; xacc[i][2]=0.f; xacc[i][3]=0.f; }
        gemm_n64(a_lane, b_lane, SM_AX_HI, SM_AX_LO, SM_WX_HI, SM_WX_LO, xacc);
        float* xps = xp_smem;   // buffer 0
        #pragma unroll
        for (int nt = 0; nt < 8; nt++) {
            int cl = nt * 8 + tg * 2;
            int b0 = mg * 16 + grp;
            xps[cl * 68 + b0]           = xacc[nt][0];
            xps[(cl + 1) * 68 + b0]     = xacc[nt][1];
            xps[cl * 68 + b0 + 8]       = xacc[nt][2];
            xps[(cl + 1) * 68 + b0 + 8] = xacc[nt][3];
        }
    }
    __syncthreads();

    // ---- time loop ----
    for (int t = 0; t < T_STEPS; t++) {
        const int par = t & 1;

        if (is_h) {
            // 1) localized elem-wait: h(t-1) producers = cgs [kg*8, kg*8+8)
            if (t > 0 && t128 < 8) {
                wait_ge(&g_elem[(kg * 8 + t128) * CPAD], 4u * (unsigned)t);
            }
            BAR_H();
            // 2) stage h(t-1) tile
            stage_tile128(smem, SM_AH_HI, SM_AH_LO,
                          g_h_hi[par ^ 1] + kg * KSL, g_h_lo[par ^ 1] + kg * KSL, t128);
            BAR_H();
            // 3) h-GEMM
            float acc[8][4];
            #pragma unroll
            for (int i = 0; i < 8; i++) { acc[i][0]=0.f; acc[i][1]=0.f; acc[i][2]=0.f; acc[i][3]=0.f; }
            gemm_n64(a_lane, b_lane, SM_AH_HI, SM_AH_LO, SM_WH_HI, SM_WH_LO, acc);
            // 4) hp = acc + xp[par] -> global
            {
                float* hp = g_hp[par][kg];
                const float* xps = xp_smem + par * (64 * 68);
                #pragma unroll
                for (int nt = 0; nt < 8; nt++) {
                    int cl  = nt * 8 + tg * 2;
                    int b0  = mg * 16 + grp;
                    int col = cg * 64 + cl;
                    hp[col * B_SZ + b0]           = acc[nt][0] + xps[cl * 68 + b0];
                    hp[(col + 1) * B_SZ + b0]     = acc[nt][1] + xps[(cl + 1) * 68 + b0];
                    hp[col * B_SZ + b0 + 8]       = acc[nt][2] + xps[cl * 68 + b0 + 8];
                    hp[(col + 1) * B_SZ + b0 + 8] = acc[nt][3] + xps[(cl + 1) * 68 + b0 + 8];
                }
            }
            if (t128 == 0) {
                signal(&g_ph[cg * CPAD]);
                wait_ge(&g_ph[cg * CPAD], 4u * (unsigned)(t + 1));
            }
            BAR_H();
            // 5) elementwise (2 elems per thread)
            {
                const float* hp0 = g_hp[par][0];
                const float* hp1 = g_hp[par][1];
                const float* hp2 = g_hp[par][2];
                const float* hp3 = g_hp[par][3];
                #pragma unroll
                for (int i = 0; i < 2; i++) {
                    int e   = t128 + i * 128;
                    int eb  = e >> 2;
                    int ejj = e & 3;
                    int ej  = cg * 16 + kg * 4 + ejj;
                    float gate[4];
                    #pragma unroll
                    for (int g = 0; g < 4; g++) {
                        int np  = g * 16 + kg * 4 + ejj;
                        int idx = (cg * 64 + np) * B_SZ + eb;
                        gate[g] = sbias[g * 4 + ejj]
                                + hp0[idx] + hp1[idx] + hp2[idx] + hp3[idx];
                    }
                    float f  = sigmoidf_fast(gate[0]);
                    float ii = sigmoidf_fast(gate[1]);
                    float cd = tanhf_fast(gate[2]);
                    float o  = sigmoidf_fast(gate[3]);
                    cs[i] = f * cs[i] + ii * cd;
                    float h = o * tanhf_fast(cs[i]);
                    hl[i] = h;
                    __nv_bfloat16 hh = __float2bfloat16_rn(h);
                    g_h_hi[par][eb * H_SZ + ej] = hh;
                    g_h_lo[par][eb * H_SZ + ej] = __float2bfloat16_rn(h - __bfloat162float(hh));
                    out[(size_t)t * (B_SZ * H_SZ) + eb * H_SZ + ej] = h;
                }
            }
            BAR_H();
            if (t128 == 0) signal(&g_elem[cg * CPAD]);
        } else {
            // x-side: produce xpart(t+1) -> xp_smem[(t+1)&1]
            if (t + 1 < T_STEPS) {
                size_t off = (size_t)(t + 1) * B_SZ * I_SZ + kg * KSL;
                stage_tile128(smem, SM_AX_HI, SM_AX_LO, g_x_hi + off, g_x_lo + off, t128);
                BAR_X();
                float xacc[8][4];
                #pragma unroll
                for (int i = 0; i < 8; i++) { xacc[i][0]=0.f; xacc[i][1]=0.f; xacc[i][2]=0.f; xacc[i][3]=0.f; }
                gemm_n64(a_lane, b_lane, SM_AX_HI, SM_AX_LO, SM_WX_HI, SM_WX_LO, xacc);
                float* xps = xp_smem + ((t + 1) & 1) * (64 * 68);
                #pragma unroll
                for (int nt = 0; nt < 8; nt++) {
                    int cl = nt * 8 + tg * 2;
                    int b0 = mg * 16 + grp;
                    xps[cl * 68 + b0]           = xacc[nt][0];
                    xps[(cl + 1) * 68 + b0]     = xacc[nt][1];
                    xps[cl * 68 + b0 + 8]       = xacc[nt][2];
                    xps[(cl + 1) * 68 + b0 + 8] = xacc[nt][3];
                }
            }
        }

        __syncthreads();   // hand xp[(t+1)&1] to h-side; protect AH/AX reuse
    }

    // final states
    if (is_h) {
        size_t base = (size_t)T_STEPS * B_SZ * H_SZ;
        #pragma unroll
        for (int i = 0; i < 2; i++) {
            int e   = t128 + i * 128;
            int eb  = e >> 2;
            int ejj = e & 3;
            int ej  = cg * 16 + kg * 4 + ejj;
            out[base + eb * H_SZ + ej] = hl[i];
            out[base + B_SZ * H_SZ + eb * H_SZ + ej] = cs[i];
        }
    }
}

extern "C" void kernel_launch(void* const* d_in, const int* in_sizes, int n_in,
                              void* d_out, int out_size)
{
    (void)in_sizes; (void)n_in; (void)out_size;
    const float* x       = (const float*)d_in[0];
    const float* hidden0 = (const float*)d_in[1];
    const float* cell0   = (const float*)d_in[2];
    const float* W       = (const float*)d_in[3];
    const float* bias    = (const float*)d_in[4];
    float* out = (float*)d_out;

    void* a0 = nullptr; void* a1 = nullptr; void* a2 = nullptr;
    cudaGetSymbolAddress(&a0, g_ph);
    cudaGetSymbolAddress(&a1, g_elem);
    cudaGetSymbolAddress(&a2, g_init);
    cudaMemsetAsync(a0, 0, sizeof(unsigned) * 32 * CPAD);
    cudaMemsetAsync(a1, 0, sizeof(unsigned) * 32 * CPAD);
    cudaMemsetAsync(a2, 0, sizeof(unsigned));

    cudaFuncSetAttribute(lstm_wspec_kernel,
                         cudaFuncAttributeMaxDynamicSharedMemorySize, SM_TOTAL);

    lstm_wspec_kernel<<<NCTA, NTHR, SM_TOTAL>>>(x, hidden0, cell0, W, bias, out);
}